// round 9
// baseline (speedup 1.0000x reference)
#include <cuda_runtime.h>
#include <cstdint>
#include <cstddef>

#define N_NODES 12288
#define IN_F    256
#define OUT_F   64
#define JSPLIT  3
#define JRANGE  (N_NODES / JSPLIT)   // 4096
#define BI      128                  // i-rows per CTA
#define NTILES  (JRANGE / 64)        // 64

// ---------------- scratch ----------------
__device__ float        g_ht[OUT_F * N_NODES];                 // h transposed fp32
__device__ unsigned     g_amax[OUT_F];                         // per-feature |h| max (bits)
__device__ __align__(256) signed char g_q1[OUT_F * N_NODES];   // level-1 s8 (f-major)
__device__ __align__(256) signed char g_q2[OUT_F * N_NODES];   // level-2 s8
__device__ float        g_part[JSPLIT][N_NODES * OUT_F];
__device__ int          g_deg[JSPLIT][N_NODES];

// ---------------- helpers ----------------
__device__ __forceinline__ uint32_t smem_u32(const void* p) {
    uint32_t a;
    asm("{ .reg .u64 t; cvta.to.shared.u64 t, %1; cvt.u32.u64 %0, t; }"
        : "=r"(a) : "l"(p));
    return a;
}
__device__ __forceinline__ void sts32(uint32_t addr, uint32_t v) {
    asm volatile("st.shared.b32 [%0], %1;" :: "r"(addr), "r"(v) : "memory");
}
__device__ __forceinline__ void cp_async16(uint32_t dst, const void* src) {
    asm volatile("cp.async.cg.shared.global [%0], [%1], 16;" :: "r"(dst), "l"(src) : "memory");
}
__device__ __forceinline__ void ldsm4(uint32_t* r, uint32_t addr) {
    asm volatile("ldmatrix.sync.aligned.m8n8.x4.shared.b16 {%0,%1,%2,%3}, [%4];"
        : "=r"(r[0]), "=r"(r[1]), "=r"(r[2]), "=r"(r[3]) : "r"(addr));
}
__device__ __forceinline__ void mma_s8(int* c, const uint32_t* a, uint32_t b0, uint32_t b1) {
    asm volatile(
        "mma.sync.aligned.m16n8k32.row.col.s32.s8.s8.s32 "
        "{%0,%1,%2,%3},{%4,%5,%6,%7},{%8,%9},{%0,%1,%2,%3};"
        : "+r"(c[0]), "+r"(c[1]), "+r"(c[2]), "+r"(c[3])
        : "r"(a[0]), "r"(a[1]), "r"(a[2]), "r"(a[3]), "r"(b0), "r"(b1));
}
// pack 4 ints (0/1) into 4 bytes
__device__ __forceinline__ uint32_t pack01(int4 v) {
    uint32_t t0 = __byte_perm((uint32_t)v.x, (uint32_t)v.y, 0x0040);
    uint32_t t1 = __byte_perm((uint32_t)v.z, (uint32_t)v.w, 0x0040);
    return __byte_perm(t0, t1, 0x5410);
}
// 64B-row swizzle: XOR 16B-chunk index (bits 4-5) with (row>>1)&3
__device__ __forceinline__ uint32_t sw64(uint32_t off) {
    return off ^ ((off >> 3) & 0x30u);
}

// =================== Kernel 0: zero amax ===================
__global__ void k_zero() {
    if (threadIdx.x < OUT_F) g_amax[threadIdx.x] = 0u;
}

// =================== Kernel 1: h = x @ W, transposed fp32 + column amax ===================
__global__ void __launch_bounds__(256)
k_gemm_h(const float* __restrict__ x, const float* __restrict__ W) {
    __shared__ float x_s[32][129];
    __shared__ float w_s[32][OUT_F];
    const int tid = threadIdx.x;
    const int ti  = tid & 31;
    const int tf  = tid >> 5;
    const int rBase = blockIdx.x * 32;

    float acc[8] = {0.f,0.f,0.f,0.f,0.f,0.f,0.f,0.f};

    #pragma unroll
    for (int xh = 0; xh < 2; xh++) {
        __syncthreads();
        #pragma unroll
        for (int k = 0; k < 4; k++) {
            int idx = tid + k * 256;
            int row = idx >> 5;
            int c4  = (idx & 31) << 2;
            float4 v = *reinterpret_cast<const float4*>(
                x + (size_t)(rBase + row) * IN_F + xh * 128 + c4);
            x_s[row][c4 + 0] = v.x; x_s[row][c4 + 1] = v.y;
            x_s[row][c4 + 2] = v.z; x_s[row][c4 + 3] = v.w;
        }
        for (int kc = 0; kc < 4; kc++) {
            __syncthreads();
            #pragma unroll
            for (int m = 0; m < 2; m++) {
                int idx = tid + m * 256;
                int row = idx >> 4;
                int c4  = (idx & 15) << 2;
                *reinterpret_cast<float4*>(&w_s[row][c4]) =
                    *reinterpret_cast<const float4*>(
                        W + (size_t)(xh * 128 + kc * 32 + row) * OUT_F + c4);
            }
            __syncthreads();
            #pragma unroll 8
            for (int kk = 0; kk < 32; kk++) {
                float xv = x_s[ti][kc * 32 + kk];
                float4 w0 = *reinterpret_cast<const float4*>(&w_s[kk][tf * 8]);
                float4 w1 = *reinterpret_cast<const float4*>(&w_s[kk][tf * 8 + 4]);
                acc[0] += xv * w0.x; acc[1] += xv * w0.y;
                acc[2] += xv * w0.z; acc[3] += xv * w0.w;
                acc[4] += xv * w1.x; acc[5] += xv * w1.y;
                acc[6] += xv * w1.z; acc[7] += xv * w1.w;
            }
        }
    }

    int j = rBase + ti;
    #pragma unroll
    for (int u = 0; u < 8; u++) {
        int f = tf * 8 + u;
        g_ht[(size_t)f * N_NODES + j] = acc[u];
        float m = fabsf(acc[u]);
        #pragma unroll
        for (int s = 16; s > 0; s >>= 1)
            m = fmaxf(m, __shfl_xor_sync(0xffffffffu, m, s));
        if (ti == 0) atomicMax(&g_amax[f], __float_as_uint(m));
    }
}

// =================== Kernel 2: two-level s8 quantization ===================
// q1 = clamp(rint(h/s1)), s1 = amax/127; q2 = clamp(rint((h - s1*q1)/s2)), s2 = s1/254.
__global__ void __launch_bounds__(256)
k_quant() {
    const int f  = blockIdx.y;
    const int j4 = (blockIdx.x * 256 + threadIdx.x) * 4;    // grid.x = 12
    float amax = fmaxf(__uint_as_float(g_amax[f]), 1e-20f);
    float s1   = amax * (1.f / 127.f);
    float inv1 = 1.f / s1;
    float s2   = s1 * (1.f / 254.f);
    float inv2 = 1.f / s2;

    float4 h = *reinterpret_cast<const float4*>(&g_ht[(size_t)f * N_NODES + j4]);
    float hv[4] = {h.x, h.y, h.z, h.w};
    signed char c1[4], c2[4];
    #pragma unroll
    for (int u = 0; u < 4; u++) {
        float q1 = fminf(fmaxf(rintf(hv[u] * inv1), -127.f), 127.f);
        float r  = hv[u] - s1 * q1;
        float q2 = fminf(fmaxf(rintf(r * inv2), -127.f), 127.f);
        c1[u] = (signed char)(int)q1;
        c2[u] = (signed char)(int)q2;
    }
    *reinterpret_cast<char4*>(&g_q1[(size_t)f * N_NODES + j4]) =
        make_char4(c1[0], c1[1], c1[2], c1[3]);
    *reinterpret_cast<char4*>(&g_q2[(size_t)f * N_NODES + j4]) =
        make_char4(c2[0], c2[1], c2[2], c2[3]);
}

// =================== Kernel 3: s8 IMMA masked aggregation ===================
// partial[js][i,f] = s1_f*(mask@q1)[i,f] + s2_f*(mask@q2)[i,f]
// smem: A s8 [2][128*64] @0 (16K), B s8 [3][2 lvl][64*64] @16384 (24K), amax @40960
#define SMEM_AGG 42240
__global__ void __launch_bounds__(256, 2)
k_aggregate(const int* __restrict__ adj) {
    extern __shared__ __align__(128) unsigned char smem[];
    const int tid   = threadIdx.x;
    const int lane  = tid & 31;
    const int w     = tid >> 5;
    const int wm    = w & 1;        // M half (64 rows)
    const int wn    = w >> 1;       // 16-feature chunk
    const int iBase = blockIdx.x * BI;
    const int js    = blockIdx.y;
    const int jBeg  = js * JRANGE;

    const uint32_t sbase = (smem_u32(smem) + 1023u) & ~1023u;
    const uint32_t offA  = sbase;
    const uint32_t offB  = sbase + 16384;
    float* sAmax = reinterpret_cast<float*>(smem + (sbase - smem_u32(smem)) + 40960);

    if (tid < OUT_F)
        sAmax[tid] = fmaxf(__uint_as_float(g_amax[tid]), 1e-20f);

    // ---- staging geometry ----
    // A: 8 int4/thread: row = k*16 + (tid>>4), 4 j-bytes at (tid&15)*4
    const int4* aT = reinterpret_cast<const int4*>(
        adj + (size_t)(iBase + (tid >> 4)) * N_NODES + jBeg) + (tid & 15);
    const uint32_t aStOff = (uint32_t)(tid >> 4) * 64 +
        (((uint32_t)(tid & 15) * 4) ^ ((((uint32_t)(tid >> 4) >> 1) & 3) << 4));
    // B: 1 chunk/level/thread: feat row = tid>>2, 16B chunk (tid&3)
    const signed char* b1T = g_q1 + (size_t)(tid >> 2) * N_NODES + jBeg + (tid & 3) * 16;
    const signed char* b2T = g_q2 + (size_t)(tid >> 2) * N_NODES + jBeg + (tid & 3) * 16;
    const uint32_t bStOff = sw64((uint32_t)(tid >> 2) * 64 + (uint32_t)(tid & 3) * 16);

    // ---- ldmatrix lane offsets (kk=0; kk=1 is ^32) ----
    const uint32_t rowA = (uint32_t)(wm * 64 + (lane & 7) + ((lane >> 3) & 1) * 8);
    const uint32_t aLd  = rowA * 64 +
        (((uint32_t)((lane >> 4) & 1) << 4) ^ (((rowA >> 1) & 3) << 4) ^ ((rowA >> 1) & 2) * 16);
    // NOTE: swizzle mask is 2 bits (bits 4-5): recompute cleanly below
    const uint32_t swmA = ((rowA >> 1) & 3) << 4;
    const uint32_t aLd0 = rowA * 64 + ((((uint32_t)((lane >> 4) & 1) << 4)) ^ swmA);
    const uint32_t rowB = (uint32_t)(wn * 16 + (lane & 15));
    const uint32_t swmB = ((rowB >> 1) & 3) << 4;
    const uint32_t bLd0 = rowB * 64 + ((((uint32_t)((lane >> 4) & 1) << 4)) ^ swmB);
    (void)aLd;

    // ---- prologue: tile 0 ----
    cp_async16(offB + bStOff, b1T);
    cp_async16(offB + 4096 + bStOff, b2T);
    asm volatile("cp.async.commit_group;" ::: "memory");
    const signed char* b1C = b1T + 64;
    const signed char* b2C = b2T + 64;

    uint32_t rP[8];
    int dacc[8] = {0,0,0,0,0,0,0,0};
    #pragma unroll
    for (int k = 0; k < 8; k++) {
        uint32_t p = pack01(__ldg(aT + (size_t)k * 16 * (N_NODES / 4)));
        dacc[k] = __dp4a((int)p, 0x01010101, dacc[k]);
        rP[k] = p;
    }
    aT += 16;

    int acc[2][4][2][4];
    #pragma unroll
    for (int l = 0; l < 2; l++)
        #pragma unroll
        for (int mi = 0; mi < 4; mi++)
            #pragma unroll
            for (int nf = 0; nf < 2; nf++)
                #pragma unroll
                for (int q = 0; q < 4; q++) acc[l][mi][nf][q] = 0;

    for (int t = 0; t < NTILES; t++) {
        const uint32_t aBuf = offA + (uint32_t)(t & 1) * 8192;
        const uint32_t bBuf = offB + (uint32_t)(t % 3) * 8192;

        // 1. STS A(t)
        #pragma unroll
        for (int k = 0; k < 8; k++)
            sts32(aBuf + aStOff + (uint32_t)k * 1024, rP[k]);

        // 2. prefetch tile t+1
        if (t + 1 < NTILES) {
            uint32_t bDst = offB + (uint32_t)((t + 1) % 3) * 8192;
            cp_async16(bDst + bStOff, b1C);
            cp_async16(bDst + 4096 + bStOff, b2C);
            asm volatile("cp.async.commit_group;" ::: "memory");
            b1C += 64; b2C += 64;
            #pragma unroll
            for (int k = 0; k < 8; k++) {
                uint32_t p = pack01(__ldg(aT + (size_t)k * 16 * (N_NODES / 4)));
                dacc[k] = __dp4a((int)p, 0x01010101, dacc[k]);
                rP[k] = p;
            }
            aT += 16;
            asm volatile("cp.async.wait_group 1;" ::: "memory");
        } else {
            asm volatile("cp.async.wait_group 0;" ::: "memory");
        }
        __syncthreads();

        // 3. IMMA on tile t (kk = k32 step; kk=1 flips bit 5)
        #pragma unroll
        for (int kk = 0; kk < 2; kk++) {
            const uint32_t kx = (uint32_t)kk << 5;
            uint32_t B1[4], B2[4];
            ldsm4(B1, bBuf + (bLd0 ^ kx));
            ldsm4(B2, bBuf + 4096 + (bLd0 ^ kx));
            #pragma unroll
            for (int mi = 0; mi < 4; mi++) {
                uint32_t A[4];
                ldsm4(A, aBuf + ((aLd0 ^ kx) + (uint32_t)mi * 1024));
                mma_s8(acc[0][mi][0], A, B1[0], B1[2]);
                mma_s8(acc[0][mi][1], A, B1[1], B1[3]);
                mma_s8(acc[1][mi][0], A, B2[0], B2[2]);
                mma_s8(acc[1][mi][1], A, B2[1], B2[3]);
            }
        }
        __syncthreads();
    }

    // ---- epilogue: dequant + combine levels, write partials ----
    {
        const int g8 = lane >> 2;
        const int cp = (lane & 3) * 2;
        #pragma unroll
        for (int nf = 0; nf < 2; nf++) {
            int col = wn * 16 + nf * 8 + cp;
            float s1a = sAmax[col]     * (1.f / 127.f);
            float s1b = sAmax[col + 1] * (1.f / 127.f);
            #pragma unroll
            for (int mi = 0; mi < 4; mi++) {
                int r = iBase + wm * 64 + mi * 16 + g8;
                float2 v0, v1;
                v0.x = s1a * ((float)acc[0][mi][nf][0] + (float)acc[1][mi][nf][0] * (1.f / 254.f));
                v0.y = s1b * ((float)acc[0][mi][nf][1] + (float)acc[1][mi][nf][1] * (1.f / 254.f));
                v1.x = s1a * ((float)acc[0][mi][nf][2] + (float)acc[1][mi][nf][2] * (1.f / 254.f));
                v1.y = s1b * ((float)acc[0][mi][nf][3] + (float)acc[1][mi][nf][3] * (1.f / 254.f));
                *reinterpret_cast<float2*>(&g_part[js][(size_t)r * OUT_F + col]) = v0;
                *reinterpret_cast<float2*>(&g_part[js][(size_t)(r + 8) * OUT_F + col]) = v1;
            }
        }
    }

    // degree: dacc[k] -> row k*16 + (tid>>4), partial over lanes (tid&15)
    #pragma unroll
    for (int k = 0; k < 8; k++) {
        int v = dacc[k];
        v += __shfl_down_sync(0xffffffffu, v, 8, 16);
        v += __shfl_down_sync(0xffffffffu, v, 4, 16);
        v += __shfl_down_sync(0xffffffffu, v, 2, 16);
        v += __shfl_down_sync(0xffffffffu, v, 1, 16);
        if ((tid & 15) == 0)
            g_deg[js][iBase + k * 16 + (tid >> 4)] = v;
    }
}

// ================ Kernel 4: out = elu(sum(partials)/deg) ================
__global__ void __launch_bounds__(256)
k_finalize(float* __restrict__ out) {
    int g = blockIdx.x * 256 + threadIdx.x;
    int i = g >> 6;
    float s = g_part[0][g] + g_part[1][g] + g_part[2][g];
    float d = (float)(g_deg[0][i] + g_deg[1][i] + g_deg[2][i]);
    float v = s / d;
    out[g] = (v > 0.f) ? v : expm1f(v);
}

// =========================== launch ===========================
extern "C" void kernel_launch(void* const* d_in, const int* in_sizes, int n_in,
                              void* d_out, int out_size) {
    const int* adj = nullptr;
    const float* x = nullptr;
    const float* W = nullptr;
    for (int k = 0; k < n_in; k++) {
        long long sz = in_sizes[k];
        if (sz == (long long)N_NODES * N_NODES)      adj = (const int*)d_in[k];
        else if (sz == (long long)N_NODES * IN_F)    x = (const float*)d_in[k];
        else if (sz == (long long)IN_F * OUT_F)      W = (const float*)d_in[k];
    }
    float* out = (float*)d_out;

    cudaFuncSetAttribute(k_aggregate, cudaFuncAttributeMaxDynamicSharedMemorySize, SMEM_AGG);

    k_zero<<<1, 64>>>();
    k_gemm_h<<<N_NODES / 32, 256>>>(x, W);
    k_quant<<<dim3(N_NODES / 1024, OUT_F), 256>>>();
    k_aggregate<<<dim3(N_NODES / BI, JSPLIT), 256, SMEM_AGG>>>(adj);
    k_finalize<<<(N_NODES * OUT_F) / 256, 256>>>(out);
}

// round 10
// speedup vs baseline: 2.7306x; 2.7306x over previous
#include <cuda_runtime.h>
#include <cuda_fp16.h>
#include <cstdint>
#include <cstddef>

#define N_NODES 12288
#define IN_F    256
#define OUT_F   64
#define JSPLIT  3
#define JRANGE  (N_NODES / JSPLIT)   // 4096
#define BI      128                  // i-rows per CTA
#define NTILES  (JRANGE / 64)        // 64

// h as fp16, transposed (feature-major): g_qt[f][j]
__device__ __half g_qt[OUT_F * N_NODES];               // 1.6 MB
__device__ float  g_part[JSPLIT][N_NODES * OUT_F];     // 9.4 MB
__device__ int    g_deg[JSPLIT][N_NODES];

// ---------------- helpers ----------------
__device__ __forceinline__ uint32_t smem_u32(const void* p) {
    uint32_t a;
    asm("{ .reg .u64 t; cvta.to.shared.u64 t, %1; cvt.u32.u64 %0, t; }"
        : "=r"(a) : "l"(p));
    return a;
}
__device__ __forceinline__ void sts64(uint32_t addr, uint32_t a, uint32_t b) {
    asm volatile("st.shared.v2.b32 [%0], {%1,%2};" :: "r"(addr), "r"(a), "r"(b) : "memory");
}
__device__ __forceinline__ void cp_async16(uint32_t dst, const void* src) {
    asm volatile("cp.async.cg.shared.global [%0], [%1], 16;" :: "r"(dst), "l"(src) : "memory");
}
__device__ __forceinline__ void ldsm4(uint32_t* r, uint32_t addr) {
    asm volatile("ldmatrix.sync.aligned.m8n8.x4.shared.b16 {%0,%1,%2,%3}, [%4];"
        : "=r"(r[0]), "=r"(r[1]), "=r"(r[2]), "=r"(r[3]) : "r"(addr));
}
__device__ __forceinline__ void mma16816(float* c, const uint32_t* a,
                                         uint32_t b0, uint32_t b1) {
    asm volatile(
        "mma.sync.aligned.m16n8k16.row.col.f32.f16.f16.f32 "
        "{%0,%1,%2,%3},{%4,%5,%6,%7},{%8,%9},{%0,%1,%2,%3};"
        : "+f"(c[0]), "+f"(c[1]), "+f"(c[2]), "+f"(c[3])
        : "r"(a[0]), "r"(a[1]), "r"(a[2]), "r"(a[3]), "r"(b0), "r"(b1));
}
__device__ __forceinline__ uint32_t sw128(uint32_t off) {
    return off ^ ((off >> 3) & 0x70u);
}

// ======================= Kernel 1: h = x @ W -> fp16 transposed =======================
// grid (384, 2): CTA covers 32 rows x 32 feats. High occupancy (6144 warps).
__global__ void __launch_bounds__(256)
k_gemm_h(const float* __restrict__ x, const float* __restrict__ W) {
    __shared__ float x_s[32][129];
    __shared__ float w_s[32][36];
    const int tid = threadIdx.x;
    const int ti  = tid & 31;
    const int tf  = tid >> 5;              // 0..7 -> 4 feats each
    const int rBase = blockIdx.x * 32;
    const int fBase = blockIdx.y * 32;

    float acc[4] = {0.f, 0.f, 0.f, 0.f};

    #pragma unroll
    for (int xh = 0; xh < 2; xh++) {
        __syncthreads();
        // stage x cols [xh*128, +128): 1024 float4, 4 per thread (scalar STS: row pad 129)
        #pragma unroll
        for (int k = 0; k < 4; k++) {
            int idx = tid + k * 256;
            int row = idx >> 5;
            int c4  = (idx & 31) << 2;
            float4 v = *reinterpret_cast<const float4*>(
                x + (size_t)(rBase + row) * IN_F + xh * 128 + c4);
            x_s[row][c4 + 0] = v.x; x_s[row][c4 + 1] = v.y;
            x_s[row][c4 + 2] = v.z; x_s[row][c4 + 3] = v.w;
        }
        for (int kc = 0; kc < 4; kc++) {
            __syncthreads();
            {   // stage W rows [xh*128 + kc*32, +32) x feats [fBase, +32): 1 float4/thread
                int row = tid >> 3;
                int c4  = (tid & 7) << 2;
                *reinterpret_cast<float4*>(&w_s[row][c4]) =
                    *reinterpret_cast<const float4*>(
                        W + (size_t)(xh * 128 + kc * 32 + row) * OUT_F + fBase + c4);
            }
            __syncthreads();
            #pragma unroll 8
            for (int kk = 0; kk < 32; kk++) {
                float xv = x_s[ti][kc * 32 + kk];
                float4 wv = *reinterpret_cast<const float4*>(&w_s[kk][tf * 4]);
                acc[0] += xv * wv.x; acc[1] += xv * wv.y;
                acc[2] += xv * wv.z; acc[3] += xv * wv.w;
            }
        }
    }

    int j = rBase + ti;
    #pragma unroll
    for (int u = 0; u < 4; u++)
        g_qt[(size_t)(fBase + tf * 4 + u) * N_NODES + j] = __float2half_rn(acc[u]);
}

// ======================= Kernel 2: fp16 HMMA masked aggregation =======================
// partial[js][i,f] = sum_{j in split} mask[i,j] * h_fp16[j,f]
// CTA tile 128(i) x 64(f) x 64(j). Warps 4M x 2N (M=32, N=32 each).
// smem: A fp16 [2][128][64] @0 (32KB), B fp16 [3][64][64] @32768 (24KB)
#define SMEM_AGG (32768 + 24576 + 1024)
__global__ void __launch_bounds__(256, 2)
k_aggregate(const int* __restrict__ adj) {
    extern __shared__ __align__(1024) unsigned char smem[];
    const int tid   = threadIdx.x;
    const int lane  = tid & 31;
    const int w     = tid >> 5;
    const int wm    = w & 3;        // M quarter (32 rows)
    const int wn    = w >> 2;       // N half (32 feats)
    const int iBase = blockIdx.x * BI;
    const int js    = blockIdx.y;
    const int jBeg  = js * JRANGE;

    const uint32_t sbase = (smem_u32(smem) + 1023u) & ~1023u;
    const uint32_t offA  = sbase;
    const uint32_t offB  = sbase + 32768;

    // ---- staging geometry ----
    // A: 8 int4/thread/tile: row = k*16 + (tid>>4), 4 ints at col (tid&15)*4
    const uint32_t A_SW0 = sw128((uint32_t)((tid >> 4) * 128 + (tid & 15) * 8));
    const int4* aT = reinterpret_cast<const int4*>(
        adj + (size_t)(iBase + (tid >> 4)) * N_NODES + jBeg) + (tid & 15);
    // B: 2 x 16B/thread/tile: feat row = (tid>>3) and +32, chunk (tid&7)
    const uint32_t B_SW0 = sw128((uint32_t)((tid >> 3) * 128 + (tid & 7) * 16));
    const __half* bT = g_qt + (size_t)(tid >> 3) * N_NODES + jBeg + (tid & 7) * 8;

    // ---- ldmatrix lane geometry ----
    const uint32_t a_ch = (uint32_t)((lane >> 4) << 4);
    const uint32_t AR0  = (uint32_t)((wm * 32 + (lane & 15)) * 128 + ((lane & 7) << 4));
    const int b_n       = (lane & 7) + ((lane >> 4) << 3);
    const uint32_t b_cb = (lane & 8) ? 16u : 0u;
    const uint32_t BR0  = (uint32_t)((wn * 32 + b_n) * 128 + ((b_n & 7) << 4));

    // ---- prologue: B(0) via cp.async, A(0) via LDG ----
    cp_async16(offB + B_SW0, bT);
    cp_async16(offB + 4096 + B_SW0, bT + (size_t)32 * N_NODES);
    asm volatile("cp.async.commit_group;" ::: "memory");
    const __half* bC = bT + 64;
    int4 rA[8];
    #pragma unroll
    for (int k = 0; k < 8; k++) rA[k] = __ldg(aT + (size_t)k * 16 * (N_NODES / 4));
    aT += 16;

    float acc[2][4][4];     // [mi][nj][quad]
    #pragma unroll
    for (int mi = 0; mi < 2; mi++)
        #pragma unroll
        for (int nj = 0; nj < 4; nj++)
            #pragma unroll
            for (int q = 0; q < 4; q++) acc[mi][nj][q] = 0.f;
    int dacc[8] = {0,0,0,0,0,0,0,0};

    for (int t = 0; t < NTILES; t++) {
        const uint32_t aBuf = offA + (uint32_t)(t & 1) * 16384;
        const uint32_t bBuf = offB + (uint32_t)(t % 3) * 8192;

        // 1. convert + STS A(t) as fp16 0/1; degree via dp4a
        #pragma unroll
        for (int k = 0; k < 8; k++) {
            uint32_t t0 = __byte_perm((uint32_t)rA[k].x, (uint32_t)rA[k].y, 0x7430);
            uint32_t t1 = __byte_perm((uint32_t)rA[k].z, (uint32_t)rA[k].w, 0x7430);
            dacc[k] = __dp4a((int)t0, 0x01010101, dacc[k]);
            dacc[k] = __dp4a((int)t1, 0x01010101, dacc[k]);
            sts64(aBuf + A_SW0 + (uint32_t)k * 2048, t0 * 0x3C00u, t1 * 0x3C00u);
        }
        // 2. prefetch tile t+1
        if (t + 1 < NTILES) {
            uint32_t bDst = offB + (uint32_t)((t + 1) % 3) * 8192;
            cp_async16(bDst + B_SW0, bC);
            cp_async16(bDst + 4096 + B_SW0, bC + (size_t)32 * N_NODES);
            asm volatile("cp.async.commit_group;" ::: "memory");
            bC += 64;
            #pragma unroll
            for (int k = 0; k < 8; k++) rA[k] = __ldg(aT + (size_t)k * 16 * (N_NODES / 4));
            aT += 16;
            asm volatile("cp.async.wait_group 1;" ::: "memory");
        } else {
            asm volatile("cp.async.wait_group 0;" ::: "memory");
        }
        __syncthreads();

        // 3. HMMA on tile t
        #pragma unroll
        for (int kk = 0; kk < 4; kk++) {
            const uint32_t cb = (uint32_t)(kk * 32);
            uint32_t B0[4], B1[4];
            ldsm4(B0, (bBuf + BR0)        ^ (cb + b_cb));   // feats wn*32 + 0..15
            ldsm4(B1, (bBuf + BR0 + 2048) ^ (cb + b_cb));   // feats wn*32 + 16..31
            #pragma unroll
            for (int mi = 0; mi < 2; mi++) {
                uint32_t A0[4];
                ldsm4(A0, (aBuf + AR0 + (uint32_t)mi * 2048) ^ (cb + a_ch));
                mma16816(acc[mi][0], A0, B0[0], B0[1]);
                mma16816(acc[mi][1], A0, B0[2], B0[3]);
                mma16816(acc[mi][2], A0, B1[0], B1[1]);
                mma16816(acc[mi][3], A0, B1[2], B1[3]);
            }
        }
        __syncthreads();
    }

    // ---- epilogue: write partials ----
    {
        const int g8 = lane >> 2;
        const int cp = (lane & 3) * 2;
        #pragma unroll
        for (int mi = 0; mi < 2; mi++) {
            int r = iBase + wm * 32 + mi * 16 + g8;
            #pragma unroll
            for (int nj = 0; nj < 4; nj++) {
                int col = wn * 32 + nj * 8 + cp;
                float2 v0 = make_float2(acc[mi][nj][0], acc[mi][nj][1]);
                float2 v1 = make_float2(acc[mi][nj][2], acc[mi][nj][3]);
                *reinterpret_cast<float2*>(&g_part[js][(size_t)r * OUT_F + col]) = v0;
                *reinterpret_cast<float2*>(&g_part[js][(size_t)(r + 8) * OUT_F + col]) = v1;
            }
        }
    }

    // degree: dacc[k] -> row k*16 + (tid>>4), partial over lanes (tid&15)
    #pragma unroll
    for (int k = 0; k < 8; k++) {
        int v = dacc[k];
        v += __shfl_down_sync(0xffffffffu, v, 8, 16);
        v += __shfl_down_sync(0xffffffffu, v, 4, 16);
        v += __shfl_down_sync(0xffffffffu, v, 2, 16);
        v += __shfl_down_sync(0xffffffffu, v, 1, 16);
        if ((tid & 15) == 0)
            g_deg[js][iBase + k * 16 + (tid >> 4)] = v;
    }
}

// ================ Kernel 3: out = elu(sum(partials)/deg) ================
__global__ void __launch_bounds__(256)
k_finalize(float* __restrict__ out) {
    int g = blockIdx.x * 256 + threadIdx.x;
    int i = g >> 6;
    float s = g_part[0][g] + g_part[1][g] + g_part[2][g];
    float d = (float)(g_deg[0][i] + g_deg[1][i] + g_deg[2][i]);
    float v = s / d;
    out[g] = (v > 0.f) ? v : expm1f(v);
}

// =========================== launch ===========================
extern "C" void kernel_launch(void* const* d_in, const int* in_sizes, int n_in,
                              void* d_out, int out_size) {
    const int* adj = nullptr;
    const float* x = nullptr;
    const float* W = nullptr;
    for (int k = 0; k < n_in; k++) {
        long long sz = in_sizes[k];
        if (sz == (long long)N_NODES * N_NODES)      adj = (const int*)d_in[k];
        else if (sz == (long long)N_NODES * IN_F)    x = (const float*)d_in[k];
        else if (sz == (long long)IN_F * OUT_F)      W = (const float*)d_in[k];
    }
    float* out = (float*)d_out;

    cudaFuncSetAttribute(k_aggregate, cudaFuncAttributeMaxDynamicSharedMemorySize, SMEM_AGG);

    k_gemm_h<<<dim3(N_NODES / 32, 2), 256>>>(x, W);
    k_aggregate<<<dim3(N_NODES / BI, JSPLIT), 256, SMEM_AGG>>>(adj);
    k_finalize<<<(N_NODES * OUT_F) / 256, 256>>>(out);
}

// round 11
// speedup vs baseline: 2.7942x; 1.0233x over previous
#include <cuda_runtime.h>
#include <cuda_fp16.h>
#include <cstdint>
#include <cstddef>

#define N_NODES 12288
#define IN_F    256
#define OUT_F   64
#define JSPLIT  3
#define JRANGE  (N_NODES / JSPLIT)   // 4096
#define BI      128                  // i-rows per CTA
#define NTILES  (JRANGE / 64)        // 64

// h as fp16, transposed (feature-major): g_qt[f][j]
__device__ __half g_qt[OUT_F * N_NODES];               // 1.6 MB
__device__ float  g_part[JSPLIT][N_NODES * OUT_F];     // 9.4 MB
__device__ int    g_deg[JSPLIT][N_NODES];

// ---------------- helpers ----------------
__device__ __forceinline__ uint32_t smem_u32(const void* p) {
    uint32_t a;
    asm("{ .reg .u64 t; cvta.to.shared.u64 t, %1; cvt.u32.u64 %0, t; }"
        : "=r"(a) : "l"(p));
    return a;
}
__device__ __forceinline__ void sts64(uint32_t addr, uint32_t a, uint32_t b) {
    asm volatile("st.shared.v2.b32 [%0], {%1,%2};" :: "r"(addr), "r"(a), "r"(b) : "memory");
}
__device__ __forceinline__ void cp_async16(uint32_t dst, const void* src) {
    asm volatile("cp.async.cg.shared.global [%0], [%1], 16;" :: "r"(dst), "l"(src) : "memory");
}
__device__ __forceinline__ void ldsm4(uint32_t* r, uint32_t addr) {
    asm volatile("ldmatrix.sync.aligned.m8n8.x4.shared.b16 {%0,%1,%2,%3}, [%4];"
        : "=r"(r[0]), "=r"(r[1]), "=r"(r[2]), "=r"(r[3]) : "r"(addr));
}
__device__ __forceinline__ void mma16816(float* c, const uint32_t* a,
                                         uint32_t b0, uint32_t b1) {
    asm volatile(
        "mma.sync.aligned.m16n8k16.row.col.f32.f16.f16.f32 "
        "{%0,%1,%2,%3},{%4,%5,%6,%7},{%8,%9},{%0,%1,%2,%3};"
        : "+f"(c[0]), "+f"(c[1]), "+f"(c[2]), "+f"(c[3])
        : "r"(a[0]), "r"(a[1]), "r"(a[2]), "r"(a[3]), "r"(b0), "r"(b1));
}
__device__ __forceinline__ uint32_t sw128(uint32_t off) {
    return off ^ ((off >> 3) & 0x70u);
}

// ======================= Kernel 1: h = x @ W -> fp16 transposed =======================
// 128 threads/CTA, CTA = 32 rows x 64 feats; thread = 1 row x 16 feats.
// x LDS amortized over 16 FFMA; w_s reads warp-uniform (broadcast). fma-issue bound.
__global__ void __launch_bounds__(128)
k_gemm_h(const float* __restrict__ x, const float* __restrict__ W) {
    __shared__ float x_s[32][129];
    __shared__ float w_s[32][68];
    const int tid = threadIdx.x;
    const int ti  = tid & 31;            // row
    const int tf  = tid >> 5;            // 0..3 -> 16 feats each (warp-uniform)
    const int rBase = blockIdx.x * 32;

    float acc[16];
    #pragma unroll
    for (int u = 0; u < 16; u++) acc[u] = 0.f;

    #pragma unroll
    for (int xh = 0; xh < 2; xh++) {
        __syncthreads();
        // stage x cols [xh*128, +128): 1024 float4, 8 per thread
        #pragma unroll
        for (int k = 0; k < 8; k++) {
            int idx = tid + k * 128;
            int row = idx >> 5;
            int c4  = (idx & 31) << 2;
            float4 v = *reinterpret_cast<const float4*>(
                x + (size_t)(rBase + row) * IN_F + xh * 128 + c4);
            x_s[row][c4 + 0] = v.x; x_s[row][c4 + 1] = v.y;
            x_s[row][c4 + 2] = v.z; x_s[row][c4 + 3] = v.w;
        }
        for (int kc = 0; kc < 4; kc++) {
            __syncthreads();
            // stage W rows [xh*128 + kc*32, +32) x 64 feats: 512 float4, 4 per thread
            #pragma unroll
            for (int m = 0; m < 4; m++) {
                int idx = tid + m * 128;
                int row = idx >> 4;
                int c4  = (idx & 15) << 2;
                *reinterpret_cast<float4*>(&w_s[row][c4]) =
                    *reinterpret_cast<const float4*>(
                        W + (size_t)(xh * 128 + kc * 32 + row) * OUT_F + c4);
            }
            __syncthreads();
            #pragma unroll 8
            for (int kk = 0; kk < 32; kk++) {
                float xv = x_s[ti][kc * 32 + kk];
                float4 w0 = *reinterpret_cast<const float4*>(&w_s[kk][tf * 16 + 0]);
                float4 w1 = *reinterpret_cast<const float4*>(&w_s[kk][tf * 16 + 4]);
                float4 w2 = *reinterpret_cast<const float4*>(&w_s[kk][tf * 16 + 8]);
                float4 w3 = *reinterpret_cast<const float4*>(&w_s[kk][tf * 16 + 12]);
                acc[0]  += xv * w0.x; acc[1]  += xv * w0.y;
                acc[2]  += xv * w0.z; acc[3]  += xv * w0.w;
                acc[4]  += xv * w1.x; acc[5]  += xv * w1.y;
                acc[6]  += xv * w1.z; acc[7]  += xv * w1.w;
                acc[8]  += xv * w2.x; acc[9]  += xv * w2.y;
                acc[10] += xv * w2.z; acc[11] += xv * w2.w;
                acc[12] += xv * w3.x; acc[13] += xv * w3.y;
                acc[14] += xv * w3.z; acc[15] += xv * w3.w;
            }
        }
    }

    const int j = rBase + ti;
    #pragma unroll
    for (int u = 0; u < 16; u++)
        g_qt[(size_t)(tf * 16 + u) * N_NODES + j] = __float2half_rn(acc[u]);
}

// ======================= Kernel 2: fp16 HMMA masked aggregation (unchanged from R10) ==========
// partial[js][i,f] = sum_{j in split} mask[i,j] * h_fp16[j,f]
// CTA tile 128(i) x 64(f) x 64(j). Warps 4M x 2N (M=32, N=32 each).
// smem: A fp16 [2][128][64] @0 (32KB), B fp16 [3][64][64] @32768 (24KB)
#define SMEM_AGG (32768 + 24576 + 1024)
__global__ void __launch_bounds__(256, 2)
k_aggregate(const int* __restrict__ adj) {
    extern __shared__ __align__(1024) unsigned char smem[];
    const int tid   = threadIdx.x;
    const int lane  = tid & 31;
    const int w     = tid >> 5;
    const int wm    = w & 3;        // M quarter (32 rows)
    const int wn    = w >> 2;       // N half (32 feats)
    const int iBase = blockIdx.x * BI;
    const int js    = blockIdx.y;
    const int jBeg  = js * JRANGE;

    const uint32_t sbase = (smem_u32(smem) + 1023u) & ~1023u;
    const uint32_t offA  = sbase;
    const uint32_t offB  = sbase + 32768;

    // ---- staging geometry ----
    const uint32_t A_SW0 = sw128((uint32_t)((tid >> 4) * 128 + (tid & 15) * 8));
    const int4* aT = reinterpret_cast<const int4*>(
        adj + (size_t)(iBase + (tid >> 4)) * N_NODES + jBeg) + (tid & 15);
    const uint32_t B_SW0 = sw128((uint32_t)((tid >> 3) * 128 + (tid & 7) * 16));
    const __half* bT = g_qt + (size_t)(tid >> 3) * N_NODES + jBeg + (tid & 7) * 8;

    // ---- ldmatrix lane geometry ----
    const uint32_t a_ch = (uint32_t)((lane >> 4) << 4);
    const uint32_t AR0  = (uint32_t)((wm * 32 + (lane & 15)) * 128 + ((lane & 7) << 4));
    const int b_n       = (lane & 7) + ((lane >> 4) << 3);
    const uint32_t b_cb = (lane & 8) ? 16u : 0u;
    const uint32_t BR0  = (uint32_t)((wn * 32 + b_n) * 128 + ((b_n & 7) << 4));

    // ---- prologue ----
    cp_async16(offB + B_SW0, bT);
    cp_async16(offB + 4096 + B_SW0, bT + (size_t)32 * N_NODES);
    asm volatile("cp.async.commit_group;" ::: "memory");
    const __half* bC = bT + 64;
    int4 rA[8];
    #pragma unroll
    for (int k = 0; k < 8; k++) rA[k] = __ldg(aT + (size_t)k * 16 * (N_NODES / 4));
    aT += 16;

    float acc[2][4][4];
    #pragma unroll
    for (int mi = 0; mi < 2; mi++)
        #pragma unroll
        for (int nj = 0; nj < 4; nj++)
            #pragma unroll
            for (int q = 0; q < 4; q++) acc[mi][nj][q] = 0.f;
    int dacc[8] = {0,0,0,0,0,0,0,0};

    for (int t = 0; t < NTILES; t++) {
        const uint32_t aBuf = offA + (uint32_t)(t & 1) * 16384;
        const uint32_t bBuf = offB + (uint32_t)(t % 3) * 8192;

        // 1. convert + STS A(t) as fp16 0/1; degree via dp4a
        #pragma unroll
        for (int k = 0; k < 8; k++) {
            uint32_t t0 = __byte_perm((uint32_t)rA[k].x, (uint32_t)rA[k].y, 0x7430);
            uint32_t t1 = __byte_perm((uint32_t)rA[k].z, (uint32_t)rA[k].w, 0x7430);
            dacc[k] = __dp4a((int)t0, 0x01010101, dacc[k]);
            dacc[k] = __dp4a((int)t1, 0x01010101, dacc[k]);
            sts64(aBuf + A_SW0 + (uint32_t)k * 2048, t0 * 0x3C00u, t1 * 0x3C00u);
        }
        // 2. prefetch tile t+1
        if (t + 1 < NTILES) {
            uint32_t bDst = offB + (uint32_t)((t + 1) % 3) * 8192;
            cp_async16(bDst + B_SW0, bC);
            cp_async16(bDst + 4096 + B_SW0, bC + (size_t)32 * N_NODES);
            asm volatile("cp.async.commit_group;" ::: "memory");
            bC += 64;
            #pragma unroll
            for (int k = 0; k < 8; k++) rA[k] = __ldg(aT + (size_t)k * 16 * (N_NODES / 4));
            aT += 16;
            asm volatile("cp.async.wait_group 1;" ::: "memory");
        } else {
            asm volatile("cp.async.wait_group 0;" ::: "memory");
        }
        __syncthreads();

        // 3. HMMA on tile t
        #pragma unroll
        for (int kk = 0; kk < 4; kk++) {
            const uint32_t cb = (uint32_t)(kk * 32);
            uint32_t B0[4], B1[4];
            ldsm4(B0, (bBuf + BR0)        ^ (cb + b_cb));
            ldsm4(B1, (bBuf + BR0 + 2048) ^ (cb + b_cb));
            #pragma unroll
            for (int mi = 0; mi < 2; mi++) {
                uint32_t A0[4];
                ldsm4(A0, (aBuf + AR0 + (uint32_t)mi * 2048) ^ (cb + a_ch));
                mma16816(acc[mi][0], A0, B0[0], B0[1]);
                mma16816(acc[mi][1], A0, B0[2], B0[3]);
                mma16816(acc[mi][2], A0, B1[0], B1[1]);
                mma16816(acc[mi][3], A0, B1[2], B1[3]);
            }
        }
        __syncthreads();
    }

    // ---- epilogue: write partials ----
    {
        const int g8 = lane >> 2;
        const int cp = (lane & 3) * 2;
        #pragma unroll
        for (int mi = 0; mi < 2; mi++) {
            int r = iBase + wm * 32 + mi * 16 + g8;
            #pragma unroll
            for (int nj = 0; nj < 4; nj++) {
                int col = wn * 32 + nj * 8 + cp;
                float2 v0 = make_float2(acc[mi][nj][0], acc[mi][nj][1]);
                float2 v1 = make_float2(acc[mi][nj][2], acc[mi][nj][3]);
                *reinterpret_cast<float2*>(&g_part[js][(size_t)r * OUT_F + col]) = v0;
                *reinterpret_cast<float2*>(&g_part[js][(size_t)(r + 8) * OUT_F + col]) = v1;
            }
        }
    }

    // degree
    #pragma unroll
    for (int k = 0; k < 8; k++) {
        int v = dacc[k];
        v += __shfl_down_sync(0xffffffffu, v, 8, 16);
        v += __shfl_down_sync(0xffffffffu, v, 4, 16);
        v += __shfl_down_sync(0xffffffffu, v, 2, 16);
        v += __shfl_down_sync(0xffffffffu, v, 1, 16);
        if ((tid & 15) == 0)
            g_deg[js][iBase + k * 16 + (tid >> 4)] = v;
    }
}

// ================ Kernel 3: out = elu(sum(partials)/deg) ================
__global__ void __launch_bounds__(256)
k_finalize(float* __restrict__ out) {
    int g = blockIdx.x * 256 + threadIdx.x;
    int i = g >> 6;
    float s = g_part[0][g] + g_part[1][g] + g_part[2][g];
    float d = (float)(g_deg[0][i] + g_deg[1][i] + g_deg[2][i]);
    float v = s / d;
    out[g] = (v > 0.f) ? v : expm1f(v);
}

// =========================== launch ===========================
extern "C" void kernel_launch(void* const* d_in, const int* in_sizes, int n_in,
                              void* d_out, int out_size) {
    const int* adj = nullptr;
    const float* x = nullptr;
    const float* W = nullptr;
    for (int k = 0; k < n_in; k++) {
        long long sz = in_sizes[k];
        if (sz == (long long)N_NODES * N_NODES)      adj = (const int*)d_in[k];
        else if (sz == (long long)N_NODES * IN_F)    x = (const float*)d_in[k];
        else if (sz == (long long)IN_F * OUT_F)      W = (const float*)d_in[k];
    }
    float* out = (float*)d_out;

    cudaFuncSetAttribute(k_aggregate, cudaFuncAttributeMaxDynamicSharedMemorySize, SMEM_AGG);

    k_gemm_h<<<N_NODES / 32, 128>>>(x, W);
    k_aggregate<<<dim3(N_NODES / BI, JSPLIT), 256, SMEM_AGG>>>(adj);
    k_finalize<<<(N_NODES * OUT_F) / 256, 256>>>(out);
}

// round 12
// speedup vs baseline: 2.8156x; 1.0077x over previous
#include <cuda_runtime.h>
#include <cuda_fp16.h>
#include <cstdint>
#include <cstddef>

#define N_NODES 12288
#define IN_F    256
#define OUT_F   64
#define JSPLIT  3
#define JRANGE  (N_NODES / JSPLIT)   // 4096
#define BI      128                  // i-rows per CTA
#define NTILES  (JRANGE / 64)        // 64

// h as fp16, transposed (feature-major): g_qt[f][j]
__device__ __half g_qt[OUT_F * N_NODES];               // 1.6 MB
__device__ float  g_part[JSPLIT][N_NODES * OUT_F];     // 9.4 MB
__device__ int    g_deg[JSPLIT][N_NODES];

// ---------------- helpers ----------------
__device__ __forceinline__ uint32_t smem_u32(const void* p) {
    uint32_t a;
    asm("{ .reg .u64 t; cvta.to.shared.u64 t, %1; cvt.u32.u64 %0, t; }"
        : "=r"(a) : "l"(p));
    return a;
}
__device__ __forceinline__ void sts64(uint32_t addr, uint32_t a, uint32_t b) {
    asm volatile("st.shared.v2.b32 [%0], {%1,%2};" :: "r"(addr), "r"(a), "r"(b) : "memory");
}
__device__ __forceinline__ void cp_async16(uint32_t dst, const void* src) {
    asm volatile("cp.async.cg.shared.global [%0], [%1], 16;" :: "r"(dst), "l"(src) : "memory");
}
__device__ __forceinline__ void ldsm4(uint32_t* r, uint32_t addr) {
    asm volatile("ldmatrix.sync.aligned.m8n8.x4.shared.b16 {%0,%1,%2,%3}, [%4];"
        : "=r"(r[0]), "=r"(r[1]), "=r"(r[2]), "=r"(r[3]) : "r"(addr));
}
__device__ __forceinline__ void mma16816(float* c, const uint32_t* a,
                                         uint32_t b0, uint32_t b1) {
    asm volatile(
        "mma.sync.aligned.m16n8k16.row.col.f32.f16.f16.f32 "
        "{%0,%1,%2,%3},{%4,%5,%6,%7},{%8,%9},{%0,%1,%2,%3};"
        : "+f"(c[0]), "+f"(c[1]), "+f"(c[2]), "+f"(c[3])
        : "r"(a[0]), "r"(a[1]), "r"(a[2]), "r"(a[3]), "r"(b0), "r"(b1));
}
__device__ __forceinline__ uint32_t sw128(uint32_t off) {
    return off ^ ((off >> 3) & 0x70u);
}

// ======================= Kernel 1: h = x @ W -> fp16 transposed =======================
// One-shot staging (W 256x68, x 32x257 fp32 in smem), ONE barrier, zero barriers in
// the 256-k FFMA loop. 128 thr/CTA: thread = 1 row (lane) x 16 feats (warp-uniform).
#define WS_LD  68                          // W row pad (272B, 16B-aligned)
#define XS_LD  257                         // x row pad (bank = ti + k, conflict-free)
#define SMEM_GH ((IN_F * WS_LD + 32 * XS_LD) * 4)   // 102528 B
__global__ void __launch_bounds__(128, 2)
k_gemm_h(const float* __restrict__ x, const float* __restrict__ W) {
    extern __shared__ float sm[];
    float* w_s = sm;                       // [256][68]
    float* x_s = sm + IN_F * WS_LD;        // [32][257]
    const int tid = threadIdx.x;
    const int ti  = tid & 31;              // row within CTA tile
    const int tf  = tid >> 5;              // 0..3 -> 16 feats (warp-uniform)
    const int rBase = blockIdx.x * 32;

    // stage W: 4096 float4, 32 per thread (row pad 272B keeps 16B alignment)
    #pragma unroll
    for (int m = 0; m < 32; m++) {
        int idx = tid + m * 128;
        int row = idx >> 4;
        int c4  = (idx & 15) << 2;
        float4 v = *reinterpret_cast<const float4*>(W + (size_t)row * OUT_F + c4);
        *reinterpret_cast<float4*>(&w_s[row * WS_LD + c4]) = v;
    }
    // stage x: 2048 float4, 16 per thread (scalar STS: 257 pad breaks 16B align)
    #pragma unroll
    for (int m = 0; m < 16; m++) {
        int idx = tid + m * 128;
        int row = idx >> 6;
        int c4  = (idx & 63) << 2;
        float4 v = *reinterpret_cast<const float4*>(
            x + (size_t)(rBase + row) * IN_F + c4);
        float* dst = &x_s[row * XS_LD + c4];
        dst[0] = v.x; dst[1] = v.y; dst[2] = v.z; dst[3] = v.w;
    }
    __syncthreads();

    float acc[16];
    #pragma unroll
    for (int u = 0; u < 16; u++) acc[u] = 0.f;

    const float* xr = &x_s[ti * XS_LD];
    const float* wr = &w_s[tf * 16];
    #pragma unroll 8
    for (int k = 0; k < IN_F; k++) {
        float xv = xr[k];
        float4 w0 = *reinterpret_cast<const float4*>(wr + k * WS_LD + 0);
        float4 w1 = *reinterpret_cast<const float4*>(wr + k * WS_LD + 4);
        float4 w2 = *reinterpret_cast<const float4*>(wr + k * WS_LD + 8);
        float4 w3 = *reinterpret_cast<const float4*>(wr + k * WS_LD + 12);
        acc[0]  += xv * w0.x; acc[1]  += xv * w0.y;
        acc[2]  += xv * w0.z; acc[3]  += xv * w0.w;
        acc[4]  += xv * w1.x; acc[5]  += xv * w1.y;
        acc[6]  += xv * w1.z; acc[7]  += xv * w1.w;
        acc[8]  += xv * w2.x; acc[9]  += xv * w2.y;
        acc[10] += xv * w2.z; acc[11] += xv * w2.w;
        acc[12] += xv * w3.x; acc[13] += xv * w3.y;
        acc[14] += xv * w3.z; acc[15] += xv * w3.w;
    }

    const int j = rBase + ti;
    #pragma unroll
    for (int u = 0; u < 16; u++)
        g_qt[(size_t)(tf * 16 + u) * N_NODES + j] = __float2half_rn(acc[u]);
}

// ======================= Kernel 2: fp16 HMMA masked aggregation (unchanged) ==========
// partial[js][i,f] = sum_{j in split} mask[i,j] * h_fp16[j,f]
// CTA tile 128(i) x 64(f) x 64(j). Warps 4M x 2N (M=32, N=32 each).
// smem: A fp16 [2][128][64] @0 (32KB), B fp16 [3][64][64] @32768 (24KB)
#define SMEM_AGG (32768 + 24576 + 1024)
__global__ void __launch_bounds__(256, 2)
k_aggregate(const int* __restrict__ adj) {
    extern __shared__ __align__(1024) unsigned char smem[];
    const int tid   = threadIdx.x;
    const int lane  = tid & 31;
    const int w     = tid >> 5;
    const int wm    = w & 3;        // M quarter (32 rows)
    const int wn    = w >> 2;       // N half (32 feats)
    const int iBase = blockIdx.x * BI;
    const int js    = blockIdx.y;
    const int jBeg  = js * JRANGE;

    const uint32_t sbase = (smem_u32(smem) + 1023u) & ~1023u;
    const uint32_t offA  = sbase;
    const uint32_t offB  = sbase + 32768;

    // ---- staging geometry ----
    const uint32_t A_SW0 = sw128((uint32_t)((tid >> 4) * 128 + (tid & 15) * 8));
    const int4* aT = reinterpret_cast<const int4*>(
        adj + (size_t)(iBase + (tid >> 4)) * N_NODES + jBeg) + (tid & 15);
    const uint32_t B_SW0 = sw128((uint32_t)((tid >> 3) * 128 + (tid & 7) * 16));
    const __half* bT = g_qt + (size_t)(tid >> 3) * N_NODES + jBeg + (tid & 7) * 8;

    // ---- ldmatrix lane geometry ----
    const uint32_t a_ch = (uint32_t)((lane >> 4) << 4);
    const uint32_t AR0  = (uint32_t)((wm * 32 + (lane & 15)) * 128 + ((lane & 7) << 4));
    const int b_n       = (lane & 7) + ((lane >> 4) << 3);
    const uint32_t b_cb = (lane & 8) ? 16u : 0u;
    const uint32_t BR0  = (uint32_t)((wn * 32 + b_n) * 128 + ((b_n & 7) << 4));

    // ---- prologue ----
    cp_async16(offB + B_SW0, bT);
    cp_async16(offB + 4096 + B_SW0, bT + (size_t)32 * N_NODES);
    asm volatile("cp.async.commit_group;" ::: "memory");
    const __half* bC = bT + 64;
    int4 rA[8];
    #pragma unroll
    for (int k = 0; k < 8; k++) rA[k] = __ldg(aT + (size_t)k * 16 * (N_NODES / 4));
    aT += 16;

    float acc[2][4][4];
    #pragma unroll
    for (int mi = 0; mi < 2; mi++)
        #pragma unroll
        for (int nj = 0; nj < 4; nj++)
            #pragma unroll
            for (int q = 0; q < 4; q++) acc[mi][nj][q] = 0.f;
    int dacc[8] = {0,0,0,0,0,0,0,0};

    for (int t = 0; t < NTILES; t++) {
        const uint32_t aBuf = offA + (uint32_t)(t & 1) * 16384;
        const uint32_t bBuf = offB + (uint32_t)(t % 3) * 8192;

        // 1. convert + STS A(t) as fp16 0/1; degree via dp4a
        #pragma unroll
        for (int k = 0; k < 8; k++) {
            uint32_t t0 = __byte_perm((uint32_t)rA[k].x, (uint32_t)rA[k].y, 0x7430);
            uint32_t t1 = __byte_perm((uint32_t)rA[k].z, (uint32_t)rA[k].w, 0x7430);
            dacc[k] = __dp4a((int)t0, 0x01010101, dacc[k]);
            dacc[k] = __dp4a((int)t1, 0x01010101, dacc[k]);
            sts64(aBuf + A_SW0 + (uint32_t)k * 2048, t0 * 0x3C00u, t1 * 0x3C00u);
        }
        // 2. prefetch tile t+1
        if (t + 1 < NTILES) {
            uint32_t bDst = offB + (uint32_t)((t + 1) % 3) * 8192;
            cp_async16(bDst + B_SW0, bC);
            cp_async16(bDst + 4096 + B_SW0, bC + (size_t)32 * N_NODES);
            asm volatile("cp.async.commit_group;" ::: "memory");
            bC += 64;
            #pragma unroll
            for (int k = 0; k < 8; k++) rA[k] = __ldg(aT + (size_t)k * 16 * (N_NODES / 4));
            aT += 16;
            asm volatile("cp.async.wait_group 1;" ::: "memory");
        } else {
            asm volatile("cp.async.wait_group 0;" ::: "memory");
        }
        __syncthreads();

        // 3. HMMA on tile t
        #pragma unroll
        for (int kk = 0; kk < 4; kk++) {
            const uint32_t cb = (uint32_t)(kk * 32);
            uint32_t B0[4], B1[4];
            ldsm4(B0, (bBuf + BR0)        ^ (cb + b_cb));
            ldsm4(B1, (bBuf + BR0 + 2048) ^ (cb + b_cb));
            #pragma unroll
            for (int mi = 0; mi < 2; mi++) {
                uint32_t A0[4];
                ldsm4(A0, (aBuf + AR0 + (uint32_t)mi * 2048) ^ (cb + a_ch));
                mma16816(acc[mi][0], A0, B0[0], B0[1]);
                mma16816(acc[mi][1], A0, B0[2], B0[3]);
                mma16816(acc[mi][2], A0, B1[0], B1[1]);
                mma16816(acc[mi][3], A0, B1[2], B1[3]);
            }
        }
        __syncthreads();
    }

    // ---- epilogue: write partials ----
    {
        const int g8 = lane >> 2;
        const int cp = (lane & 3) * 2;
        #pragma unroll
        for (int mi = 0; mi < 2; mi++) {
            int r = iBase + wm * 32 + mi * 16 + g8;
            #pragma unroll
            for (int nj = 0; nj < 4; nj++) {
                int col = wn * 32 + nj * 8 + cp;
                float2 v0 = make_float2(acc[mi][nj][0], acc[mi][nj][1]);
                float2 v1 = make_float2(acc[mi][nj][2], acc[mi][nj][3]);
                *reinterpret_cast<float2*>(&g_part[js][(size_t)r * OUT_F + col]) = v0;
                *reinterpret_cast<float2*>(&g_part[js][(size_t)(r + 8) * OUT_F + col]) = v1;
            }
        }
    }

    // degree
    #pragma unroll
    for (int k = 0; k < 8; k++) {
        int v = dacc[k];
        v += __shfl_down_sync(0xffffffffu, v, 8, 16);
        v += __shfl_down_sync(0xffffffffu, v, 4, 16);
        v += __shfl_down_sync(0xffffffffu, v, 2, 16);
        v += __shfl_down_sync(0xffffffffu, v, 1, 16);
        if ((tid & 15) == 0)
            g_deg[js][iBase + k * 16 + (tid >> 4)] = v;
    }
}

// ================ Kernel 3: out = elu(sum(partials)/deg) ================
__global__ void __launch_bounds__(256)
k_finalize(float* __restrict__ out) {
    int g = blockIdx.x * 256 + threadIdx.x;
    int i = g >> 6;
    float s = g_part[0][g] + g_part[1][g] + g_part[2][g];
    float d = (float)(g_deg[0][i] + g_deg[1][i] + g_deg[2][i]);
    float v = s / d;
    out[g] = (v > 0.f) ? v : expm1f(v);
}

// =========================== launch ===========================
extern "C" void kernel_launch(void* const* d_in, const int* in_sizes, int n_in,
                              void* d_out, int out_size) {
    const int* adj = nullptr;
    const float* x = nullptr;
    const float* W = nullptr;
    for (int k = 0; k < n_in; k++) {
        long long sz = in_sizes[k];
        if (sz == (long long)N_NODES * N_NODES)      adj = (const int*)d_in[k];
        else if (sz == (long long)N_NODES * IN_F)    x = (const float*)d_in[k];
        else if (sz == (long long)IN_F * OUT_F)      W = (const float*)d_in[k];
    }
    float* out = (float*)d_out;

    cudaFuncSetAttribute(k_gemm_h, cudaFuncAttributeMaxDynamicSharedMemorySize, SMEM_GH);
    cudaFuncSetAttribute(k_aggregate, cudaFuncAttributeMaxDynamicSharedMemorySize, SMEM_AGG);

    k_gemm_h<<<N_NODES / 32, 128, SMEM_GH>>>(x, W);
    k_aggregate<<<dim3(N_NODES / BI, JSPLIT), 256, SMEM_AGG>>>(adj);
    k_finalize<<<(N_NODES * OUT_F) / 256, 256>>>(out);
}